// round 9
// baseline (speedup 1.0000x reference)
#include <cuda_runtime.h>
#include <cuda_fp16.h>
#include <cstdint>

#define N_NODES 100000
#define N_EDGES 1600000
#define IN_F    512
#define OUT_F   256

// Scratch (no cudaMalloc). H and T are fp16 (range-safe: |H|<=1, |T|<~16).
__device__ __half g_H[(size_t)N_NODES * OUT_F];
__device__ __half g_T[(size_t)N_NODES * OUT_F];
__device__ int    g_row_ptr[N_NODES + 1];
// fp16 weight [512][256], 256 KB — L2-resident.
__device__ __half g_Wh[(size_t)IN_F * OUT_F];

// ---------------------------------------------------------------------------
// helpers
// ---------------------------------------------------------------------------
__device__ __forceinline__ uint32_t smem_u32(const void* p) {
    uint32_t a;
    asm("{ .reg .u64 t; cvta.to.shared.u64 t, %1; cvt.u32.u64 %0, t; }" : "=r"(a) : "l"(p));
    return a;
}
__device__ __forceinline__ void ldsm_x4(uint32_t* r, uint32_t addr) {
    asm volatile("ldmatrix.sync.aligned.m8n8.x4.shared.b16 {%0,%1,%2,%3}, [%4];"
                 : "=r"(r[0]), "=r"(r[1]), "=r"(r[2]), "=r"(r[3]) : "r"(addr));
}
__device__ __forceinline__ void ldsm_x4_t(uint32_t* r, uint32_t addr) {
    asm volatile("ldmatrix.sync.aligned.m8n8.x4.trans.shared.b16 {%0,%1,%2,%3}, [%4];"
                 : "=r"(r[0]), "=r"(r[1]), "=r"(r[2]), "=r"(r[3]) : "r"(addr));
}
__device__ __forceinline__ void mma_f16(float* c, const uint32_t* a, const uint32_t* b) {
    asm volatile(
        "mma.sync.aligned.m16n8k16.row.col.f32.f16.f16.f32 "
        "{%0,%1,%2,%3}, {%4,%5,%6,%7}, {%8,%9}, {%0,%1,%2,%3};"
        : "+f"(c[0]), "+f"(c[1]), "+f"(c[2]), "+f"(c[3])
        : "r"(a[0]), "r"(a[1]), "r"(a[2]), "r"(a[3]), "r"(b[0]), "r"(b[1]));
}
__device__ __forceinline__ void cp16(uint32_t saddr, const void* gaddr) {
    asm volatile("cp.async.cg.shared.global [%0], [%1], 16;" :: "r"(saddr), "l"(gaddr));
}
#define CP_COMMIT() asm volatile("cp.async.commit_group;" ::: "memory")
#define CP_WAIT1()  asm volatile("cp.async.wait_group 1;" ::: "memory")

// ---------------------------------------------------------------------------
// Convert W (fp32) -> fp16, once.
// ---------------------------------------------------------------------------
__global__ void wconv_kernel(const float* __restrict__ W)
{
    int i = blockIdx.x * blockDim.x + threadIdx.x;
    if (i >= IN_F * OUT_F) return;
    g_Wh[i] = __float2half_rn(W[i]);
}

// ---------------------------------------------------------------------------
// GEMM + tanh: H[M,256] = tanh(A[M,512] @ W), fp16 mma, fp32 accum.
// BM=64, BN=256, BK=32 (16 chunks). 256 threads, 8 warps (2m x 4n),
// warp tile 32x64. 2 CTAs/SM (barrier/LDG stalls of one CTA covered by the
// other). cp.async double-buffered B, register-prefetched + converted A.
// ---------------------------------------------------------------------------
#define A_PADH 40
#define B_PADH 264
#define SZ_A   (64 * A_PADH * 2)           // 5120 B per stage
#define SZ_B   (32 * B_PADH * 2)           // 16896 B per stage
#define OFF_A(st)   ((st) * SZ_A)
#define OFF_BH(st)  (2 * SZ_A + (st) * SZ_B)
#define GEMM_SMEM   (2 * SZ_A + 2 * SZ_B)  // 44032 B

__global__ __launch_bounds__(256, 2) void gemm_tanh_kernel(
    const float* __restrict__ A, __half* __restrict__ H)
{
    extern __shared__ char smem[];
    const uint32_t sb = smem_u32(smem);
    const int tid  = threadIdx.x;
    const int wid  = tid >> 5, lane = tid & 31;
    const int mwarp = wid & 1, nwarp = wid >> 1;
    const int m0 = blockIdx.x * 64;

    // A load mapping: thread -> row tid/4 (0..63), k-off (tid&3)*8
    const int arow = tid >> 2;
    const int acol = (tid & 3) * 8;
    const bool avalid = (m0 + arow) < N_NODES;
    const float* abase = A + (size_t)(m0 + arow) * IN_F + acol;

    // B copy mapping: thread -> k-row tid/8 (0..31), 32-half seg (tid&7)*32
    const int brow = tid >> 3;
    const int bh0  = (tid & 7) * 32;
    const size_t  bsrc0 = (size_t)brow * OUT_F + bh0;
    const uint32_t bSts = sb + (uint32_t)(brow * B_PADH + bh0) * 2;

    // ldmatrix lane addressing
    const int q = lane >> 3, rr = lane & 7;
    uint32_t aOff[2];
    #pragma unroll
    for (int mt = 0; mt < 2; mt++) {
        int row  = mwarp * 32 + mt * 16 + (q & 1) * 8 + rr;
        int col8 = (q >> 1) * 8;
        aOff[mt] = (uint32_t)(row * A_PADH + col8) * 2;
    }
    const uint32_t bOff = (uint32_t)((((q & 1) * 8 + rr) * B_PADH) + nwarp * 64 + (q >> 1) * 8) * 2;

    float acc[2][8][4];
    #pragma unroll
    for (int i = 0; i < 2; i++)
        #pragma unroll
        for (int j = 0; j < 8; j++)
            #pragma unroll
            for (int l = 0; l < 4; l++) acc[i][j][l] = 0.0f;

    float4 pa[2][2];
    // prologue: A chunk 0 -> regs; B chunk 0 -> smem stage 0
    if (avalid) {
        pa[0][0] = __ldg((const float4*)(abase + 0));
        pa[0][1] = __ldg((const float4*)(abase + 4));
    } else {
        pa[0][0] = pa[0][1] = make_float4(0.f, 0.f, 0.f, 0.f);
    }
    {
        const __half* sh = g_Wh + bsrc0;
        cp16(OFF_BH(0) + bSts,      sh);
        cp16(OFF_BH(0) + bSts + 16, sh + 8);
        cp16(OFF_BH(0) + bSts + 32, sh + 16);
        cp16(OFF_BH(0) + bSts + 48, sh + 24);
    }
    CP_COMMIT();

    #pragma unroll
    for (int ck = 0; ck < 16; ck++) {
        const int st = ck & 1;
        // prefetch next B into other stage
        if (ck + 1 < 16) {
            const size_t o = (size_t)(ck + 1) * 32 * OUT_F + bsrc0;
            const __half* sh = g_Wh + o;
            cp16(OFF_BH(st ^ 1) + bSts,      sh);
            cp16(OFF_BH(st ^ 1) + bSts + 16, sh + 8);
            cp16(OFF_BH(st ^ 1) + bSts + 32, sh + 16);
            cp16(OFF_BH(st ^ 1) + bSts + 48, sh + 24);
        }
        CP_COMMIT();

        // convert + store A(ck) fp32 regs -> fp16 smem stage st
        {
            __half2 h0 = __floats2half2_rn(pa[st][0].x, pa[st][0].y);
            __half2 h1 = __floats2half2_rn(pa[st][0].z, pa[st][0].w);
            __half2 h2 = __floats2half2_rn(pa[st][1].x, pa[st][1].y);
            __half2 h3 = __floats2half2_rn(pa[st][1].z, pa[st][1].w);
            uint4 u;
            u.x = *(uint32_t*)&h0; u.y = *(uint32_t*)&h1;
            u.z = *(uint32_t*)&h2; u.w = *(uint32_t*)&h3;
            *(uint4*)(smem + OFF_A(st) + (uint32_t)(arow * A_PADH + acol) * 2) = u;
        }
        // prefetch next A into regs (latency hidden by MMA below)
        if (ck + 1 < 16) {
            if (avalid) {
                pa[st ^ 1][0] = __ldg((const float4*)(abase + (ck + 1) * 32));
                pa[st ^ 1][1] = __ldg((const float4*)(abase + (ck + 1) * 32 + 4));
            }
        }
        CP_WAIT1();          // B(ck) arrived
        __syncthreads();

        // ---- MMA over stage st ----
        const uint32_t sa  = sb + OFF_A(st);
        const uint32_t sbh = sb + OFF_BH(st);
        #pragma unroll
        for (int s = 0; s < 2; s++) {
            uint32_t a[2][4];
            ldsm_x4(a[0], sa + aOff[0] + s * 32);
            ldsm_x4(a[1], sa + aOff[1] + s * 32);
            #pragma unroll
            for (int np = 0; np < 4; np++) {
                uint32_t bh[4];
                uint32_t ba = bOff + (uint32_t)(s * 16 * B_PADH + np * 16) * 2;
                ldsm_x4_t(bh, sbh + ba);
                #pragma unroll
                for (int mt = 0; mt < 2; mt++) {
                    mma_f16(acc[mt][2*np+0], a[mt], bh + 0);
                    mma_f16(acc[mt][2*np+1], a[mt], bh + 2);
                }
            }
        }
        __syncthreads();
    }

    // ---- Epilogue: tanh + fp16 store ----
    const int gid = lane >> 2, tig = lane & 3;
    #pragma unroll
    for (int mt = 0; mt < 2; mt++) {
        int row = m0 + mwarp * 32 + mt * 16 + gid;
        #pragma unroll
        for (int nt = 0; nt < 8; nt++) {
            int col = nwarp * 64 + nt * 8 + tig * 2;
            if (row < N_NODES) {
                __half2 v = __floats2half2_rn(tanhf(acc[mt][nt][0]), tanhf(acc[mt][nt][1]));
                *(__half2*)&H[(size_t)row * OUT_F + col] = v;
            }
            if (row + 8 < N_NODES) {
                __half2 v = __floats2half2_rn(tanhf(acc[mt][nt][2]), tanhf(acc[mt][nt][3]));
                *(__half2*)&H[(size_t)(row + 8) * OUT_F + col] = v;
            }
        }
    }
}

// ---------------------------------------------------------------------------
// row_ptr[i] = lower_bound(row, i)  (row is sorted)
// ---------------------------------------------------------------------------
__global__ void row_ptr_kernel(const int* __restrict__ row)
{
    int i = blockIdx.x * blockDim.x + threadIdx.x;
    if (i > N_NODES) return;
    int lo = 0, hi = N_EDGES;
    while (lo < hi) {
        int mid = (lo + hi) >> 1;
        if (row[mid] < i) lo = mid + 1; else hi = mid;
    }
    g_row_ptr[i] = lo;
}

// ---------------------------------------------------------------------------
// SpMM, software-pipelined: col/val prefetched 2 edges ahead, 512B gather
// 1 edge ahead -> per-warp MLP ~2-3 instead of 1. fp32 accumulate.
// ---------------------------------------------------------------------------
__device__ __forceinline__ void spmm_accum(
    int start, int end, int lane,
    const int* __restrict__ col, const float* __restrict__ vals,
    const __half* __restrict__ X, float* acc)
{
    int e = start;
    if (e >= end) return;

    int   cA = __ldcs(&col[e]);
    float vA = __ldcs(&vals[e]);
    int   cB = 0;
    float vB = 0.f;
    if (e + 1 < end) { cB = __ldcs(&col[e + 1]); vB = __ldcs(&vals[e + 1]); }
    uint4 xA = __ldg((const uint4*)&X[(size_t)cA * OUT_F + lane * 8]);

    while (e < end) {
        // issue next gather before consuming current
        uint4 xB = make_uint4(0, 0, 0, 0);
        if (e + 1 < end)
            xB = __ldg((const uint4*)&X[(size_t)cB * OUT_F + lane * 8]);
        // prefetch col/val two ahead
        int cN = 0; float vN = 0.f;
        if (e + 2 < end) { cN = __ldcs(&col[e + 2]); vN = __ldcs(&vals[e + 2]); }

        const __half2* hx = (const __half2*)&xA;
        #pragma unroll
        for (int j = 0; j < 4; j++) {
            float2 f = __half22float2(hx[j]);
            acc[2*j+0] = fmaf(vA, f.x, acc[2*j+0]);
            acc[2*j+1] = fmaf(vA, f.y, acc[2*j+1]);
        }

        e++;
        cA = cB; vA = vB;
        cB = cN; vB = vN;
        xA = xB;
    }
}

__global__ __launch_bounds__(256) void spmm_h2h_kernel(
    const int* __restrict__ col, const float* __restrict__ vals,
    const __half* __restrict__ X, __half* __restrict__ Y)
{
    int warp = (blockIdx.x * blockDim.x + threadIdx.x) >> 5;
    int lane = threadIdx.x & 31;
    if (warp >= N_NODES) return;
    float acc[8] = {0,0,0,0,0,0,0,0};
    spmm_accum(g_row_ptr[warp], g_row_ptr[warp + 1], lane, col, vals, X, acc);
    __half2 h0 = __floats2half2_rn(acc[0], acc[1]);
    __half2 h1 = __floats2half2_rn(acc[2], acc[3]);
    __half2 h2 = __floats2half2_rn(acc[4], acc[5]);
    __half2 h3 = __floats2half2_rn(acc[6], acc[7]);
    uint4 u;
    u.x = *(uint32_t*)&h0; u.y = *(uint32_t*)&h1;
    u.z = *(uint32_t*)&h2; u.w = *(uint32_t*)&h3;
    __stcs((uint4*)&Y[(size_t)warp * OUT_F + lane * 8], u);
}

__global__ __launch_bounds__(256) void spmm_h2f_kernel(
    const int* __restrict__ col, const float* __restrict__ vals,
    const __half* __restrict__ X, float* __restrict__ Y)
{
    int warp = (blockIdx.x * blockDim.x + threadIdx.x) >> 5;
    int lane = threadIdx.x & 31;
    if (warp >= N_NODES) return;
    float acc[8] = {0,0,0,0,0,0,0,0};
    spmm_accum(g_row_ptr[warp], g_row_ptr[warp + 1], lane, col, vals, X, acc);
    float* dst = &Y[(size_t)warp * OUT_F + lane * 8];
    __stcs((float4*)&dst[0], make_float4(acc[0], acc[1], acc[2], acc[3]));
    __stcs((float4*)&dst[4], make_float4(acc[4], acc[5], acc[6], acc[7]));
}

// ---------------------------------------------------------------------------
extern "C" void kernel_launch(void* const* d_in, const int* in_sizes, int n_in,
                              void* d_out, int out_size)
{
    const float* features = (const float*)d_in[0];
    const float* weight   = (const float*)d_in[1];
    const int*   row      = (const int*)d_in[2];
    const int*   colv     = (const int*)d_in[3];
    const float* adj      = (const float*)d_in[4];
    float*       out      = (float*)d_out;

    __half* H = nullptr;
    __half* T = nullptr;
    cudaGetSymbolAddress((void**)&H, g_H);
    cudaGetSymbolAddress((void**)&T, g_T);

    cudaFuncSetAttribute(gemm_tanh_kernel,
                         cudaFuncAttributeMaxDynamicSharedMemorySize, GEMM_SMEM);

    // 0. Convert W to fp16
    wconv_kernel<<<(IN_F * OUT_F + 255) / 256, 256>>>(weight);

    // 1. H = tanh(X @ W), fp16 output (BM=64, 2 CTAs/SM)
    gemm_tanh_kernel<<<(N_NODES + 63) / 64, 256, GEMM_SMEM>>>(features, H);

    // 2. row_ptr from sorted row
    row_ptr_kernel<<<(N_NODES + 1 + 255) / 256, 256>>>(row);

    // 3. T = A @ H   (fp16 -> fp16)
    int spmm_blocks = (N_NODES * 32 + 255) / 256;
    spmm_h2h_kernel<<<spmm_blocks, 256>>>(colv, adj, H, T);

    // 4. out = A @ T (fp16 -> fp32)
    spmm_h2f_kernel<<<spmm_blocks, 256>>>(colv, adj, T, out);
}

// round 10
// speedup vs baseline: 1.2115x; 1.2115x over previous
#include <cuda_runtime.h>
#include <cuda_fp16.h>
#include <cstdint>

#define N_NODES 100000
#define N_EDGES 1600000
#define IN_F    512
#define OUT_F   256

// Scratch (no cudaMalloc). H and T are fp16 (range-safe: |H|<=1, |T|<~16).
__device__ __half g_H[(size_t)N_NODES * OUT_F];
__device__ __half g_T[(size_t)N_NODES * OUT_F];
__device__ int    g_row_ptr[N_NODES + 1];
// fp16 weight [512][256], 256 KB — L2-resident.
__device__ __half g_Wh[(size_t)IN_F * OUT_F];

// ---------------------------------------------------------------------------
// helpers
// ---------------------------------------------------------------------------
__device__ __forceinline__ uint32_t smem_u32(const void* p) {
    uint32_t a;
    asm("{ .reg .u64 t; cvta.to.shared.u64 t, %1; cvt.u32.u64 %0, t; }" : "=r"(a) : "l"(p));
    return a;
}
__device__ __forceinline__ void ldsm_x4(uint32_t* r, uint32_t addr) {
    asm volatile("ldmatrix.sync.aligned.m8n8.x4.shared.b16 {%0,%1,%2,%3}, [%4];"
                 : "=r"(r[0]), "=r"(r[1]), "=r"(r[2]), "=r"(r[3]) : "r"(addr));
}
__device__ __forceinline__ void ldsm_x4_t(uint32_t* r, uint32_t addr) {
    asm volatile("ldmatrix.sync.aligned.m8n8.x4.trans.shared.b16 {%0,%1,%2,%3}, [%4];"
                 : "=r"(r[0]), "=r"(r[1]), "=r"(r[2]), "=r"(r[3]) : "r"(addr));
}
__device__ __forceinline__ void mma_f16(float* c, const uint32_t* a, const uint32_t* b) {
    asm volatile(
        "mma.sync.aligned.m16n8k16.row.col.f32.f16.f16.f32 "
        "{%0,%1,%2,%3}, {%4,%5,%6,%7}, {%8,%9}, {%0,%1,%2,%3};"
        : "+f"(c[0]), "+f"(c[1]), "+f"(c[2]), "+f"(c[3])
        : "r"(a[0]), "r"(a[1]), "r"(a[2]), "r"(a[3]), "r"(b[0]), "r"(b[1]));
}
__device__ __forceinline__ void cp16(uint32_t saddr, const void* gaddr) {
    asm volatile("cp.async.cg.shared.global [%0], [%1], 16;" :: "r"(saddr), "l"(gaddr));
}
#define CP_COMMIT() asm volatile("cp.async.commit_group;" ::: "memory")
#define CP_WAIT1()  asm volatile("cp.async.wait_group 1;" ::: "memory")

// ---------------------------------------------------------------------------
// Convert W (fp32) -> fp16, once.
// ---------------------------------------------------------------------------
__global__ void wconv_kernel(const float* __restrict__ W)
{
    int i = blockIdx.x * blockDim.x + threadIdx.x;
    if (i >= IN_F * OUT_F) return;
    g_Wh[i] = __float2half_rn(W[i]);
}

// ---------------------------------------------------------------------------
// GEMM + tanh: H[M,256] = tanh(A[M,512] @ W), 1-term fp16 (fp32 accum).
// BM=128, BN=256 (full), BK=32 (16 chunks). 512 threads, 16 warps (4m x 4n),
// warp tile 32x64. cp.async double-buffered B, register-prefetched A.
// (round-7 configuration — verified best)
// ---------------------------------------------------------------------------
#define A_PADH 40
#define B_PADH 264
#define SZ_A   (128 * A_PADH * 2)          // 10240 B per stage
#define SZ_B   (32 * B_PADH * 2)           // 16896 B per stage
#define OFF_A(st)   ((st) * SZ_A)
#define OFF_BH(st)  (2 * SZ_A + (st) * SZ_B)
#define GEMM_SMEM   (2 * SZ_A + 2 * SZ_B)  // 54272 B

__global__ __launch_bounds__(512, 1) void gemm_tanh_kernel(
    const float* __restrict__ A, __half* __restrict__ H)
{
    extern __shared__ char smem[];
    const uint32_t sb = smem_u32(smem);
    const int tid  = threadIdx.x;
    const int wid  = tid >> 5, lane = tid & 31;
    const int mwarp = wid & 3, nwarp = wid >> 2;
    const int m0 = blockIdx.x * 128;

    // A load mapping: thread -> row tid/4 (0..127), k-off (tid&3)*8
    const int arow = tid >> 2;
    const int acol = (tid & 3) * 8;
    const bool avalid = (m0 + arow) < N_NODES;
    const float* abase = A + (size_t)(m0 + arow) * IN_F + acol;

    // B copy mapping: thread -> k-row tid/16 (0..31), two 16B segs (tid&15)*2
    const int brow = tid >> 4;
    const int bseg = (tid & 15) * 2;
    const size_t  bsrc0 = (size_t)brow * OUT_F + bseg * 8;
    const uint32_t bSts = sb + (uint32_t)(brow * B_PADH + bseg * 8) * 2;

    // ldmatrix lane addressing
    const int q = lane >> 3, rr = lane & 7;
    uint32_t aOff[2];
    #pragma unroll
    for (int mt = 0; mt < 2; mt++) {
        int row  = mwarp * 32 + mt * 16 + (q & 1) * 8 + rr;
        int col8 = (q >> 1) * 8;
        aOff[mt] = (uint32_t)(row * A_PADH + col8) * 2;
    }
    const uint32_t bOff = (uint32_t)((((q & 1) * 8 + rr) * B_PADH) + nwarp * 64 + (q >> 1) * 8) * 2;

    float acc[2][8][4];
    #pragma unroll
    for (int i = 0; i < 2; i++)
        #pragma unroll
        for (int j = 0; j < 8; j++)
            #pragma unroll
            for (int l = 0; l < 4; l++) acc[i][j][l] = 0.0f;

    float4 pa[2][2];
    // prologue: A chunk 0 -> regs; B chunk 0 -> smem stage 0
    if (avalid) {
        pa[0][0] = __ldg((const float4*)(abase + 0));
        pa[0][1] = __ldg((const float4*)(abase + 4));
    } else {
        pa[0][0] = pa[0][1] = make_float4(0.f, 0.f, 0.f, 0.f);
    }
    {
        const __half* sh = g_Wh + bsrc0;
        cp16(OFF_BH(0) + bSts,      sh);
        cp16(OFF_BH(0) + bSts + 16, sh + 8);
    }
    CP_COMMIT();

    #pragma unroll
    for (int ck = 0; ck < 16; ck++) {
        const int st = ck & 1;
        // prefetch next B into other stage
        if (ck + 1 < 16) {
            const size_t o = (size_t)(ck + 1) * 32 * OUT_F + bsrc0;
            const __half* sh = g_Wh + o;
            cp16(OFF_BH(st ^ 1) + bSts,      sh);
            cp16(OFF_BH(st ^ 1) + bSts + 16, sh + 8);
        }
        CP_COMMIT();

        // convert + store A(ck) fp32 regs -> fp16 smem stage st
        {
            __half2 h0 = __floats2half2_rn(pa[st][0].x, pa[st][0].y);
            __half2 h1 = __floats2half2_rn(pa[st][0].z, pa[st][0].w);
            __half2 h2 = __floats2half2_rn(pa[st][1].x, pa[st][1].y);
            __half2 h3 = __floats2half2_rn(pa[st][1].z, pa[st][1].w);
            uint4 u;
            u.x = *(uint32_t*)&h0; u.y = *(uint32_t*)&h1;
            u.z = *(uint32_t*)&h2; u.w = *(uint32_t*)&h3;
            *(uint4*)(smem + OFF_A(st) + (uint32_t)(arow * A_PADH + acol) * 2) = u;
        }
        // prefetch next A into regs (latency hidden by MMA below)
        if (ck + 1 < 16) {
            if (avalid) {
                pa[st ^ 1][0] = __ldg((const float4*)(abase + (ck + 1) * 32));
                pa[st ^ 1][1] = __ldg((const float4*)(abase + (ck + 1) * 32 + 4));
            }
        }
        CP_WAIT1();          // B(ck) arrived
        __syncthreads();

        // ---- MMA over stage st ----
        const uint32_t sa  = sb + OFF_A(st);
        const uint32_t sbh = sb + OFF_BH(st);
        #pragma unroll
        for (int s = 0; s < 2; s++) {
            uint32_t a[2][4];
            ldsm_x4(a[0], sa + aOff[0] + s * 32);
            ldsm_x4(a[1], sa + aOff[1] + s * 32);
            #pragma unroll
            for (int np = 0; np < 4; np++) {
                uint32_t bh[4];
                uint32_t ba = bOff + (uint32_t)(s * 16 * B_PADH + np * 16) * 2;
                ldsm_x4_t(bh, sbh + ba);
                #pragma unroll
                for (int mt = 0; mt < 2; mt++) {
                    mma_f16(acc[mt][2*np+0], a[mt], bh + 0);
                    mma_f16(acc[mt][2*np+1], a[mt], bh + 2);
                }
            }
        }
        __syncthreads();
    }

    // ---- Epilogue: tanh + fp16 store ----
    const int gid = lane >> 2, tig = lane & 3;
    #pragma unroll
    for (int mt = 0; mt < 2; mt++) {
        int row = m0 + mwarp * 32 + mt * 16 + gid;
        #pragma unroll
        for (int nt = 0; nt < 8; nt++) {
            int col = nwarp * 64 + nt * 8 + tig * 2;
            if (row < N_NODES) {
                __half2 v = __floats2half2_rn(tanhf(acc[mt][nt][0]), tanhf(acc[mt][nt][1]));
                *(__half2*)&H[(size_t)row * OUT_F + col] = v;
            }
            if (row + 8 < N_NODES) {
                __half2 v = __floats2half2_rn(tanhf(acc[mt][nt][2]), tanhf(acc[mt][nt][3]));
                *(__half2*)&H[(size_t)(row + 8) * OUT_F + col] = v;
            }
        }
    }
}

// ---------------------------------------------------------------------------
// row_ptr[i] = lower_bound(row, i)  (row is sorted)
// ---------------------------------------------------------------------------
__global__ void row_ptr_kernel(const int* __restrict__ row)
{
    int i = blockIdx.x * blockDim.x + threadIdx.x;
    if (i > N_NODES) return;
    int lo = 0, hi = N_EDGES;
    while (lo < hi) {
        int mid = (lo + hi) >> 1;
        if (row[mid] < i) lo = mid + 1; else hi = mid;
    }
    g_row_ptr[i] = lo;
}

// ---------------------------------------------------------------------------
// SpMM: one warp per destination row, lane owns 8 halves, fp32 accumulate.
// 2-edge unroll: both independent gathers issued before either FMA block
// (MLP=2 with straight-line code, no rotating registers).
// FMA order per lane is identical to the serial loop -> bitwise-same result.
// ---------------------------------------------------------------------------
__device__ __forceinline__ void spmm_fma8(float v, const uint4& x, float* acc)
{
    const __half2* hx = (const __half2*)&x;
    #pragma unroll
    for (int j = 0; j < 4; j++) {
        float2 f = __half22float2(hx[j]);
        acc[2*j+0] = fmaf(v, f.x, acc[2*j+0]);
        acc[2*j+1] = fmaf(v, f.y, acc[2*j+1]);
    }
}

__device__ __forceinline__ void spmm_accum(
    int start, int end, int lane,
    const int* __restrict__ col, const float* __restrict__ vals,
    const __half* __restrict__ X, float* acc)
{
    int e = start;
    for (; e + 2 <= end; e += 2) {
        int   c0 = __ldcs(&col[e]);
        int   c1 = __ldcs(&col[e + 1]);
        float v0 = __ldcs(&vals[e]);
        float v1 = __ldcs(&vals[e + 1]);
        uint4 x0 = __ldg((const uint4*)&X[(size_t)c0 * OUT_F + lane * 8]);
        uint4 x1 = __ldg((const uint4*)&X[(size_t)c1 * OUT_F + lane * 8]);
        spmm_fma8(v0, x0, acc);
        spmm_fma8(v1, x1, acc);
    }
    if (e < end) {
        int   c0 = __ldcs(&col[e]);
        float v0 = __ldcs(&vals[e]);
        uint4 x0 = __ldg((const uint4*)&X[(size_t)c0 * OUT_F + lane * 8]);
        spmm_fma8(v0, x0, acc);
    }
}

__global__ __launch_bounds__(256) void spmm_h2h_kernel(
    const int* __restrict__ col, const float* __restrict__ vals,
    const __half* __restrict__ X, __half* __restrict__ Y)
{
    int warp = (blockIdx.x * blockDim.x + threadIdx.x) >> 5;
    int lane = threadIdx.x & 31;
    if (warp >= N_NODES) return;
    float acc[8] = {0,0,0,0,0,0,0,0};
    spmm_accum(g_row_ptr[warp], g_row_ptr[warp + 1], lane, col, vals, X, acc);
    __half2 h0 = __floats2half2_rn(acc[0], acc[1]);
    __half2 h1 = __floats2half2_rn(acc[2], acc[3]);
    __half2 h2 = __floats2half2_rn(acc[4], acc[5]);
    __half2 h3 = __floats2half2_rn(acc[6], acc[7]);
    uint4 u;
    u.x = *(uint32_t*)&h0; u.y = *(uint32_t*)&h1;
    u.z = *(uint32_t*)&h2; u.w = *(uint32_t*)&h3;
    __stcs((uint4*)&Y[(size_t)warp * OUT_F + lane * 8], u);
}

__global__ __launch_bounds__(256) void spmm_h2f_kernel(
    const int* __restrict__ col, const float* __restrict__ vals,
    const __half* __restrict__ X, float* __restrict__ Y)
{
    int warp = (blockIdx.x * blockDim.x + threadIdx.x) >> 5;
    int lane = threadIdx.x & 31;
    if (warp >= N_NODES) return;
    float acc[8] = {0,0,0,0,0,0,0,0};
    spmm_accum(g_row_ptr[warp], g_row_ptr[warp + 1], lane, col, vals, X, acc);
    float* dst = &Y[(size_t)warp * OUT_F + lane * 8];
    __stcs((float4*)&dst[0], make_float4(acc[0], acc[1], acc[2], acc[3]));
    __stcs((float4*)&dst[4], make_float4(acc[4], acc[5], acc[6], acc[7]));
}

// ---------------------------------------------------------------------------
extern "C" void kernel_launch(void* const* d_in, const int* in_sizes, int n_in,
                              void* d_out, int out_size)
{
    const float* features = (const float*)d_in[0];
    const float* weight   = (const float*)d_in[1];
    const int*   row      = (const int*)d_in[2];
    const int*   colv     = (const int*)d_in[3];
    const float* adj      = (const float*)d_in[4];
    float*       out      = (float*)d_out;

    __half* H = nullptr;
    __half* T = nullptr;
    cudaGetSymbolAddress((void**)&H, g_H);
    cudaGetSymbolAddress((void**)&T, g_T);

    cudaFuncSetAttribute(gemm_tanh_kernel,
                         cudaFuncAttributeMaxDynamicSharedMemorySize, GEMM_SMEM);

    // 0. Convert W to fp16
    wconv_kernel<<<(IN_F * OUT_F + 255) / 256, 256>>>(weight);

    // 1. H = tanh(X @ W), fp16 output (round-7 config: BM=128, 512 thr)
    gemm_tanh_kernel<<<(N_NODES + 127) / 128, 512, GEMM_SMEM>>>(features, H);

    // 2. row_ptr from sorted row
    row_ptr_kernel<<<(N_NODES + 1 + 255) / 256, 256>>>(row);

    // 3. T = A @ H   (fp16 -> fp16)
    int spmm_blocks = (N_NODES * 32 + 255) / 256;
    spmm_h2h_kernel<<<spmm_blocks, 256>>>(colv, adj, H, T);

    // 4. out = A @ T (fp16 -> fp32)
    spmm_h2f_kernel<<<spmm_blocks, 256>>>(colv, adj, T, out);
}

// round 14
// speedup vs baseline: 1.2190x; 1.0062x over previous
#include <cuda_runtime.h>
#include <cuda_fp16.h>
#include <cstdint>

#define N_NODES 100000
#define N_EDGES 1600000
#define IN_F    512
#define OUT_F   256

// Scratch (no cudaMalloc). H and T are fp16 (range-safe: |H|<=1, |T|<~16).
__device__ __half g_H[(size_t)N_NODES * OUT_F];
__device__ __half g_T[(size_t)N_NODES * OUT_F];
__device__ int    g_row_ptr[N_NODES + 1];
// fp16 weight [512][256], 256 KB — L2-resident.
__device__ __half g_Wh[(size_t)IN_F * OUT_F];

// ---------------------------------------------------------------------------
// helpers
// ---------------------------------------------------------------------------
__device__ __forceinline__ uint32_t smem_u32(const void* p) {
    uint32_t a;
    asm("{ .reg .u64 t; cvta.to.shared.u64 t, %1; cvt.u32.u64 %0, t; }" : "=r"(a) : "l"(p));
    return a;
}
__device__ __forceinline__ float tanh_fast(float x) {
    float y;
    asm("tanh.approx.f32 %0, %1;" : "=f"(y) : "f"(x));
    return y;
}
__device__ __forceinline__ void ldsm_x4(uint32_t* r, uint32_t addr) {
    asm volatile("ldmatrix.sync.aligned.m8n8.x4.shared.b16 {%0,%1,%2,%3}, [%4];"
                 : "=r"(r[0]), "=r"(r[1]), "=r"(r[2]), "=r"(r[3]) : "r"(addr));
}
__device__ __forceinline__ void ldsm_x4_t(uint32_t* r, uint32_t addr) {
    asm volatile("ldmatrix.sync.aligned.m8n8.x4.trans.shared.b16 {%0,%1,%2,%3}, [%4];"
                 : "=r"(r[0]), "=r"(r[1]), "=r"(r[2]), "=r"(r[3]) : "r"(addr));
}
__device__ __forceinline__ void mma_f16(float* c, const uint32_t* a, const uint32_t* b) {
    asm volatile(
        "mma.sync.aligned.m16n8k16.row.col.f32.f16.f16.f32 "
        "{%0,%1,%2,%3}, {%4,%5,%6,%7}, {%8,%9}, {%0,%1,%2,%3};"
        : "+f"(c[0]), "+f"(c[1]), "+f"(c[2]), "+f"(c[3])
        : "r"(a[0]), "r"(a[1]), "r"(a[2]), "r"(a[3]), "r"(b[0]), "r"(b[1]));
}
__device__ __forceinline__ void cp16(uint32_t saddr, const void* gaddr) {
    asm volatile("cp.async.cg.shared.global [%0], [%1], 16;" :: "r"(saddr), "l"(gaddr));
}
#define CP_COMMIT() asm volatile("cp.async.commit_group;" ::: "memory")
#define CP_WAIT1()  asm volatile("cp.async.wait_group 1;" ::: "memory")

// ---------------------------------------------------------------------------
// Convert W (fp32) -> fp16, once.
// ---------------------------------------------------------------------------
__global__ void wconv_kernel(const float* __restrict__ W)
{
    int i = blockIdx.x * blockDim.x + threadIdx.x;
    if (i >= IN_F * OUT_F) return;
    g_Wh[i] = __float2half_rn(W[i]);
}

// ---------------------------------------------------------------------------
// GEMM + tanh: H[M,256] = tanh(A[M,512] @ W), 1-term fp16 (fp32 accum).
// BM=128, BN=256 (full), BK=32 (16 chunks). 512 threads, 16 warps (4m x 4n).
// A double-buffered in smem (reg-prefetch+convert); B in a 3-stage cp.async
// ring so the post-MMA barrier can be dropped (max warp skew is 1 iteration:
// a fast warp at ck+1 writes A stage (ck+1)&1 and B stage (ck+2)%3, neither
// of which is read by a slow warp still in MMA(ck) on stages ck&1 / ck%3).
// Epilogue uses tanh.approx (MUFU) instead of software tanhf.
// ---------------------------------------------------------------------------
#define A_PADH 40
#define B_PADH 264
#define SZ_A   (128 * A_PADH * 2)          // 10240 B per stage
#define SZ_B   (32 * B_PADH * 2)           // 16896 B per stage
#define OFF_A(st)   ((st) * SZ_A)
#define OFF_BH(st)  (2 * SZ_A + (st) * SZ_B)
#define GEMM_SMEM   (2 * SZ_A + 3 * SZ_B)  // 71168 B

__global__ __launch_bounds__(512, 1) void gemm_tanh_kernel(
    const float* __restrict__ A, __half* __restrict__ H)
{
    extern __shared__ char smem[];
    const uint32_t sb = smem_u32(smem);
    const int tid  = threadIdx.x;
    const int wid  = tid >> 5, lane = tid & 31;
    const int mwarp = wid & 3, nwarp = wid >> 2;
    const int m0 = blockIdx.x * 128;

    // A load mapping: thread -> row tid/4 (0..127), k-off (tid&3)*8
    const int arow = tid >> 2;
    const int acol = (tid & 3) * 8;
    const bool avalid = (m0 + arow) < N_NODES;
    const float* abase = A + (size_t)(m0 + arow) * IN_F + acol;

    // B copy mapping: thread -> k-row tid/16 (0..31), two 16B segs (tid&15)*2
    const int brow = tid >> 4;
    const int bseg = (tid & 15) * 2;
    const size_t  bsrc0 = (size_t)brow * OUT_F + bseg * 8;
    const uint32_t bSts = sb + (uint32_t)(brow * B_PADH + bseg * 8) * 2;

    // ldmatrix lane addressing
    const int q = lane >> 3, rr = lane & 7;
    uint32_t aOff[2];
    #pragma unroll
    for (int mt = 0; mt < 2; mt++) {
        int row  = mwarp * 32 + mt * 16 + (q & 1) * 8 + rr;
        int col8 = (q >> 1) * 8;
        aOff[mt] = (uint32_t)(row * A_PADH + col8) * 2;
    }
    const uint32_t bOff = (uint32_t)((((q & 1) * 8 + rr) * B_PADH) + nwarp * 64 + (q >> 1) * 8) * 2;

    float acc[2][8][4];
    #pragma unroll
    for (int i = 0; i < 2; i++)
        #pragma unroll
        for (int j = 0; j < 8; j++)
            #pragma unroll
            for (int l = 0; l < 4; l++) acc[i][j][l] = 0.0f;

    float4 pa[2][2];
    // prologue: A chunk 0 -> regs; B chunk 0 -> smem stage 0
    if (avalid) {
        pa[0][0] = __ldg((const float4*)(abase + 0));
        pa[0][1] = __ldg((const float4*)(abase + 4));
    } else {
        pa[0][0] = pa[0][1] = make_float4(0.f, 0.f, 0.f, 0.f);
    }
    {
        const __half* sh = g_Wh + bsrc0;
        cp16(OFF_BH(0) + bSts,      sh);
        cp16(OFF_BH(0) + bSts + 16, sh + 8);
    }
    CP_COMMIT();

    #pragma unroll
    for (int ck = 0; ck < 16; ck++) {
        const int stA = ck & 1;
        const int stB = ck % 3;
        // prefetch next B into ring stage (ck+1)%3
        if (ck + 1 < 16) {
            const int stBn = (ck + 1) % 3;
            const size_t o = (size_t)(ck + 1) * 32 * OUT_F + bsrc0;
            const __half* sh = g_Wh + o;
            cp16(OFF_BH(stBn) + bSts,      sh);
            cp16(OFF_BH(stBn) + bSts + 16, sh + 8);
        }
        CP_COMMIT();

        // convert + store A(ck) fp32 regs -> fp16 smem stage stA
        {
            __half2 h0 = __floats2half2_rn(pa[stA][0].x, pa[stA][0].y);
            __half2 h1 = __floats2half2_rn(pa[stA][0].z, pa[stA][0].w);
            __half2 h2 = __floats2half2_rn(pa[stA][1].x, pa[stA][1].y);
            __half2 h3 = __floats2half2_rn(pa[stA][1].z, pa[stA][1].w);
            uint4 u;
            u.x = *(uint32_t*)&h0; u.y = *(uint32_t*)&h1;
            u.z = *(uint32_t*)&h2; u.w = *(uint32_t*)&h3;
            *(uint4*)(smem + OFF_A(stA) + (uint32_t)(arow * A_PADH + acol) * 2) = u;
        }
        // prefetch next A into regs (latency hidden by MMA below)
        if (ck + 1 < 16) {
            if (avalid) {
                pa[stA ^ 1][0] = __ldg((const float4*)(abase + (ck + 1) * 32));
                pa[stA ^ 1][1] = __ldg((const float4*)(abase + (ck + 1) * 32 + 4));
            }
        }
        CP_WAIT1();          // B(ck) arrived
        __syncthreads();

        // ---- MMA over stages (stA, stB) ----
        const uint32_t sa  = sb + OFF_A(stA);
        const uint32_t sbh = sb + OFF_BH(stB);
        #pragma unroll
        for (int s = 0; s < 2; s++) {
            uint32_t a[2][4];
            ldsm_x4(a[0], sa + aOff[0] + s * 32);
            ldsm_x4(a[1], sa + aOff[1] + s * 32);
            #pragma unroll
            for (int np = 0; np < 4; np++) {
                uint32_t bh[4];
                uint32_t ba = bOff + (uint32_t)(s * 16 * B_PADH + np * 16) * 2;
                ldsm_x4_t(bh, sbh + ba);
                #pragma unroll
                for (int mt = 0; mt < 2; mt++) {
                    mma_f16(acc[mt][2*np+0], a[mt], bh + 0);
                    mma_f16(acc[mt][2*np+1], a[mt], bh + 2);
                }
            }
        }
        // no trailing __syncthreads: 3-stage B ring + 2-stage A make the
        // 1-iteration warp skew race-free (see header comment).
    }

    // ---- Epilogue: tanh.approx + fp16 store ----
    const int gid = lane >> 2, tig = lane & 3;
    #pragma unroll
    for (int mt = 0; mt < 2; mt++) {
        int row = m0 + mwarp * 32 + mt * 16 + gid;
        #pragma unroll
        for (int nt = 0; nt < 8; nt++) {
            int col = nwarp * 64 + nt * 8 + tig * 2;
            if (row < N_NODES) {
                __half2 v = __floats2half2_rn(tanh_fast(acc[mt][nt][0]), tanh_fast(acc[mt][nt][1]));
                *(__half2*)&H[(size_t)row * OUT_F + col] = v;
            }
            if (row + 8 < N_NODES) {
                __half2 v = __floats2half2_rn(tanh_fast(acc[mt][nt][2]), tanh_fast(acc[mt][nt][3]));
                *(__half2*)&H[(size_t)(row + 8) * OUT_F + col] = v;
            }
        }
    }
}

// ---------------------------------------------------------------------------
// row_ptr[i] = lower_bound(row, i)  (row is sorted)
// ---------------------------------------------------------------------------
__global__ void row_ptr_kernel(const int* __restrict__ row)
{
    int i = blockIdx.x * blockDim.x + threadIdx.x;
    if (i > N_NODES) return;
    int lo = 0, hi = N_EDGES;
    while (lo < hi) {
        int mid = (lo + hi) >> 1;
        if (row[mid] < i) lo = mid + 1; else hi = mid;
    }
    g_row_ptr[i] = lo;
}

// ---------------------------------------------------------------------------
// SpMM: one warp per destination row, lane owns 8 halves, fp32 accumulate.
// 2-edge unroll, both gathers issued before either FMA block (round-10
// verified config).
// ---------------------------------------------------------------------------
__device__ __forceinline__ void spmm_fma8(float v, const uint4& x, float* acc)
{
    const __half2* hx = (const __half2*)&x;
    #pragma unroll
    for (int j = 0; j < 4; j++) {
        float2 f = __half22float2(hx[j]);
        acc[2*j+0] = fmaf(v, f.x, acc[2*j+0]);
        acc[2*j+1] = fmaf(v, f.y, acc[2*j+1]);
    }
}

__device__ __forceinline__ void spmm_accum(
    int start, int end, int lane,
    const int* __restrict__ col, const float* __restrict__ vals,
    const __half* __restrict__ X, float* acc)
{
    int e = start;
    for (; e + 2 <= end; e += 2) {
        int   c0 = __ldcs(&col[e]);
        int   c1 = __ldcs(&col[e + 1]);
        float v0 = __ldcs(&vals[e]);
        float v1 = __ldcs(&vals[e + 1]);
        uint4 x0 = __ldg((const uint4*)&X[(size_t)c0 * OUT_F + lane * 8]);
        uint4 x1 = __ldg((const uint4*)&X[(size_t)c1 * OUT_F + lane * 8]);
        spmm_fma8(v0, x0, acc);
        spmm_fma8(v1, x1, acc);
    }
    if (e < end) {
        int   c0 = __ldcs(&col[e]);
        float v0 = __ldcs(&vals[e]);
        uint4 x0 = __ldg((const uint4*)&X[(size_t)c0 * OUT_F + lane * 8]);
        spmm_fma8(v0, x0, acc);
    }
}

__global__ __launch_bounds__(256) void spmm_h2h_kernel(
    const int* __restrict__ col, const float* __restrict__ vals,
    const __half* __restrict__ X, __half* __restrict__ Y)
{
    int warp = (blockIdx.x * blockDim.x + threadIdx.x) >> 5;
    int lane = threadIdx.x & 31;
    if (warp >= N_NODES) return;
    float acc[8] = {0,0,0,0,0,0,0,0};
    spmm_accum(g_row_ptr[warp], g_row_ptr[warp + 1], lane, col, vals, X, acc);
    __half2 h0 = __floats2half2_rn(acc[0], acc[1]);
    __half2 h1 = __floats2half2_rn(acc[2], acc[3]);
    __half2 h2 = __floats2half2_rn(acc[4], acc[5]);
    __half2 h3 = __floats2half2_rn(acc[6], acc[7]);
    uint4 u;
    u.x = *(uint32_t*)&h0; u.y = *(uint32_t*)&h1;
    u.z = *(uint32_t*)&h2; u.w = *(uint32_t*)&h3;
    __stcs((uint4*)&Y[(size_t)warp * OUT_F + lane * 8], u);
}

__global__ __launch_bounds__(256) void spmm_h2f_kernel(
    const int* __restrict__ col, const float* __restrict__ vals,
    const __half* __restrict__ X, float* __restrict__ Y)
{
    int warp = (blockIdx.x * blockDim.x + threadIdx.x) >> 5;
    int lane = threadIdx.x & 31;
    if (warp >= N_NODES) return;
    float acc[8] = {0,0,0,0,0,0,0,0};
    spmm_accum(g_row_ptr[warp], g_row_ptr[warp + 1], lane, col, vals, X, acc);
    float* dst = &Y[(size_t)warp * OUT_F + lane * 8];
    __stcs((float4*)&dst[0], make_float4(acc[0], acc[1], acc[2], acc[3]));
    __stcs((float4*)&dst[4], make_float4(acc[4], acc[5], acc[6], acc[7]));
}

// ---------------------------------------------------------------------------
extern "C" void kernel_launch(void* const* d_in, const int* in_sizes, int n_in,
                              void* d_out, int out_size)
{
    const float* features = (const float*)d_in[0];
    const float* weight   = (const float*)d_in[1];
    const int*   row      = (const int*)d_in[2];
    const int*   colv     = (const int*)d_in[3];
    const float* adj      = (const float*)d_in[4];
    float*       out      = (float*)d_out;

    __half* H = nullptr;
    __half* T = nullptr;
    cudaGetSymbolAddress((void**)&H, g_H);
    cudaGetSymbolAddress((void**)&T, g_T);

    cudaFuncSetAttribute(gemm_tanh_kernel,
                         cudaFuncAttributeMaxDynamicSharedMemorySize, GEMM_SMEM);

    // 0. Convert W to fp16
    wconv_kernel<<<(IN_F * OUT_F + 255) / 256, 256>>>(weight);

    // 1. H = tanh(X @ W), fp16 output
    gemm_tanh_kernel<<<(N_NODES + 127) / 128, 512, GEMM_SMEM>>>(features, H);

    // 2. row_ptr from sorted row
    row_ptr_kernel<<<(N_NODES + 1 + 255) / 256, 256>>>(row);

    // 3. T = A @ H   (fp16 -> fp16)
    int spmm_blocks = (N_NODES * 32 + 255) / 256;
    spmm_h2h_kernel<<<spmm_blocks, 256>>>(colv, adj, H, T);

    // 4. out = A @ T (fp16 -> fp32)
    spmm_h2f_kernel<<<spmm_blocks, 256>>>(colv, adj, T, out);
}